// round 1
// baseline (speedup 1.0000x reference)
#include <cuda_runtime.h>

typedef unsigned long long ull;

#define M_TOTAL (64 * 2048)   // 131072 rows (BATCH*SEQ)
#define KDIM 128
#define HID 256
#define NPACK 768             // i,g,o gates only (f-gate is dead)
#define BM 64
#define BK 64
#define BN 192                // one "group": 64 i-cols | 64 g-cols | 64 o-cols
#define XS_STRIDE 68
#define SMEM_BYTES ((BK * BN + BK * XS_STRIDE) * 4)

// Scratch (no cudaMalloc allowed): packed transposed weights [k][n] and packed bias.
__device__ float g_Wt[KDIM * NPACK];
__device__ float g_bias[NPACK];

// Pack W_ih rows for gates i (0..255), g (512..767), o (768..1023) into
// W''[k][n] with n = group*192 + {0..63:i, 64..127:g, 128..191:o}, group = j/64.
__global__ void prep_kernel(const float* __restrict__ W_ih,
                            const float* __restrict__ b_ih,
                            const float* __restrict__ b_hh) {
    int id = blockIdx.x * blockDim.x + threadIdx.x;
    if (id >= KDIM * NPACK) return;
    int n = id % NPACK;
    int k = id / NPACK;
    int t = n / BN;           // group 0..3
    int l = n % BN;           // 0..191
    int gsel = l >> 6;        // 0:i 1:g 2:o
    int jj = t * 64 + (l & 63);
    int src = (gsel == 0 ? 0 : (gsel == 1 ? 512 : 768)) + jj;
    g_Wt[k * NPACK + n] = W_ih[src * KDIM + k];
    if (k == 0) g_bias[n] = b_ih[src] + b_hh[src];
}

__device__ __forceinline__ ull dup2(float v) {
    ull r;
    unsigned u = __float_as_uint(v);
    asm("mov.b64 %0, {%1, %1};" : "=l"(r) : "r"(u));
    return r;
}

__device__ __forceinline__ void fma2(ull& acc, ull a, ull b) {
    // Packed f32x2 FMA: 2x FFMA throughput vs FFMA-3reg on sm_103a.
    asm("fma.rn.f32x2 %0, %1, %2, %0;" : "+l"(acc) : "l"(a), "l"(b));
}

__device__ __forceinline__ float2 unpack2(ull v) {
    float2 f;
    asm("mov.b64 {%0, %1}, %2;" : "=f"(f.x), "=f"(f.y) : "l"(v));
    return f;
}

__device__ __forceinline__ float sigmoidf_fast(float x) {
    return 1.0f / (1.0f + __expf(-x));
}
__device__ __forceinline__ float tanhf_fast(float x) {
    return 2.0f / (1.0f + __expf(-2.0f * x)) - 1.0f;
}

__global__ __launch_bounds__(256, 2)
void lstm_gemm_kernel(const float* __restrict__ x, float* __restrict__ out) {
    extern __shared__ float smem[];
    float* ws = smem;                 // [BK][BN]
    float* xs = smem + BK * BN;       // [BK][XS_STRIDE], transposed x tile

    const int tid = threadIdx.x;
    const int tx = tid & 15;          // 16 col-threads * 12 cols = 192
    const int ty = tid >> 4;          // 16 row-threads * 4 rows  = 64
    const int bm = blockIdx.x * BM;
    const int grp = blockIdx.y;

    ull acc[4][6];                    // 4 rows x 6 f32x2 pairs (12 cols)
#pragma unroll
    for (int r = 0; r < 4; r++)
#pragma unroll
        for (int c = 0; c < 6; c++) acc[r][c] = 0ULL;

    for (int kt = 0; kt < 2; ++kt) {
        // Load x tile [BM][BK] -> xs transposed [BK][BM] (padded stride 68)
#pragma unroll
        for (int it = 0; it < 4; ++it) {
            int idx = it * 256 + tid;
            int m = idx >> 4;
            int kv = idx & 15;
            float4 v = *(const float4*)(x + (size_t)(bm + m) * KDIM + kt * BK + kv * 4);
            xs[(kv * 4 + 0) * XS_STRIDE + m] = v.x;
            xs[(kv * 4 + 1) * XS_STRIDE + m] = v.y;
            xs[(kv * 4 + 2) * XS_STRIDE + m] = v.z;
            xs[(kv * 4 + 3) * XS_STRIDE + m] = v.w;
        }
        // Load W'' tile [BK][BN]
#pragma unroll
        for (int it = 0; it < 12; ++it) {
            int idx = it * 256 + tid;
            int kk = idx / 48;
            int nv = idx % 48;
            float4 v = *(const float4*)(g_Wt + (size_t)(kt * BK + kk) * NPACK
                                        + grp * BN + nv * 4);
            *(float4*)(ws + kk * BN + nv * 4) = v;
        }
        __syncthreads();

#pragma unroll 8
        for (int kk = 0; kk < BK; ++kk) {
            float4 xv = *(const float4*)(xs + kk * XS_STRIDE + ty * 4);
            ull xd[4];
            xd[0] = dup2(xv.x); xd[1] = dup2(xv.y);
            xd[2] = dup2(xv.z); xd[3] = dup2(xv.w);
            const ull* wrow = (const ull*)(ws + kk * BN + tx * 12);
            ull w[6];
#pragma unroll
            for (int c = 0; c < 6; c++) w[c] = wrow[c];
#pragma unroll
            for (int r = 0; r < 4; r++)
#pragma unroll
                for (int c = 0; c < 6; c++) fma2(acc[r][c], xd[r], w[c]);
        }
        __syncthreads();
    }

    // Epilogue: exchange accumulators through smem so each thread gets
    // (i, g, o) for the same output column j, then apply gates.
    float* sg = ws;  // reuse: [BM][BN]
#pragma unroll
    for (int r = 0; r < 4; r++)
#pragma unroll
        for (int c = 0; c < 6; c++) {
            float2 v = unpack2(acc[r][c]);
            *(float2*)(sg + (ty * 4 + r) * BN + tx * 12 + 2 * c) = v;
        }
    __syncthreads();

    float* hout = out;
    float* cout = out + (size_t)M_TOTAL * HID;
#pragma unroll
    for (int it = 0; it < 16; ++it) {
        int idx = it * 256 + tid;
        int j = idx & 63;
        int m = idx >> 6;
        float gi = sg[m * BN + j]        + g_bias[grp * BN + j];
        float gG = sg[m * BN + 64 + j]   + g_bias[grp * BN + 64 + j];
        float go = sg[m * BN + 128 + j]  + g_bias[grp * BN + 128 + j];
        float ig = sigmoidf_fast(gi);
        float gg = tanhf_fast(gG);
        float og = sigmoidf_fast(go);
        float c = ig * gg;                 // f*c_prev == 0
        float h = og * tanhf_fast(c);
        size_t off = (size_t)(bm + m) * HID + grp * 64 + j;
        hout[off] = h;
        cout[off] = c;
    }
}

extern "C" void kernel_launch(void* const* d_in, const int* in_sizes, int n_in,
                              void* d_out, int out_size) {
    const float* x    = (const float*)d_in[0];
    const float* W_ih = (const float*)d_in[1];
    // d_in[2] = W_hh: unused (h_prev == 0 in the reference)
    const float* b_ih = (const float*)d_in[3];
    const float* b_hh = (const float*)d_in[4];
    float* out = (float*)d_out;

    cudaFuncSetAttribute(lstm_gemm_kernel,
                         cudaFuncAttributeMaxDynamicSharedMemorySize, SMEM_BYTES);

    prep_kernel<<<(KDIM * NPACK + 255) / 256, 256>>>(W_ih, b_ih, b_hh);

    dim3 grid(M_TOTAL / BM, 4);
    lstm_gemm_kernel<<<grid, 256, SMEM_BYTES>>>(x, out);
}

// round 3
// speedup vs baseline: 3.4077x; 3.4077x over previous
#include <cuda_runtime.h>
#include <cstdint>

#define M_TOTAL (64 * 2048)   // 131072 rows
#define KDIM 128
#define HID 256
#define NPACK 768             // i,g,o gates only (f-gate dead: c_prev == 0)
#define BM 128                // M per CTA tile
#define BJ 64                 // j per CTA (per gate) -> N = 3*64 = 192
#define NGRP 4                // 4 j-groups of 64 cover HID=256
#define CTAS_PER_GRP 256
#define ITERS 4               // m-tiles per CTA (256*4 = 1024 m-tiles per group)

#define A_STRIDE 132          // padded row stride (floats) -> conflict-free frag LDS
#define BIAS_OFF 0
#define B_OFF 192
#define B_FLOATS (8 * 3 * 16 * 64)          // 24576 floats = 96KB per group
#define A_OFF (B_OFF + B_FLOATS)            // 24768
#define SMEM_FLOATS (A_OFF + BM * A_STRIDE) // 41664
#define SMEM_BYTES (SMEM_FLOATS * 4)        // 166656 B

// ---------------- device scratch (no cudaMalloc allowed) ----------------
// g_Wp: weights pre-packed into the exact mma.sync B-fragment layout:
// [grp 4][jfrag 8][gate 3][kstep 16][lane 32][2 floats], tf32-rounded.
__device__ float g_Wp[NGRP * B_FLOATS];
__device__ float g_bias[NGRP * 192];   // [grp][gate 3][64]

__device__ __forceinline__ float to_tf32(float v) {
    uint32_t r;
    asm("cvt.rna.tf32.f32 %0, %1;" : "=r"(r) : "f"(v));
    return __uint_as_float(r);
}

__global__ void prep_kernel(const float* __restrict__ W_ih,
                            const float* __restrict__ b_ih,
                            const float* __restrict__ b_hh) {
    int d = blockIdx.x * blockDim.x + threadIdx.x;
    if (d < NGRP * 192) {   // bias: [grp][gate][64]
        int grp = d / 192, r = d % 192;
        int gate = r / 64, jl = r % 64;
        int src = (gate == 0 ? 0 : (gate == 1 ? 512 : 768)) + grp * 64 + jl;
        g_bias[d] = b_ih[src] + b_hh[src];
    }
    if (d >= NPACK * KDIM) return;
    // decompose d into B-frag layout coords
    int grp = d / B_FLOATS;          int r1 = d % B_FLOATS;
    int jf  = r1 / 3072;             int r2 = r1 % 3072;
    int gate = r2 / 1024;            int r3 = r2 % 1024;
    int ks  = r3 / 64;               int r4 = r3 % 64;
    int lane = r4 >> 1;              int b01 = r4 & 1;
    int gid = lane >> 2, tig = lane & 3;
    // mma.m16n8k8.row.col B frag: b0 = B[k=tig][n=gid], b1 = B[k=tig+4][n=gid]
    int j_global = grp * 64 + jf * 8 + gid;
    int k = ks * 8 + tig + b01 * 4;
    int src_row = (gate == 0 ? 0 : (gate == 1 ? 512 : 768)) + j_global;
    g_Wp[d] = to_tf32(W_ih[src_row * KDIM + k]);
}

// ---------------- helpers ----------------
__device__ __forceinline__ void mma_tf32(float (&dacc)[4], const uint32_t (&a)[4],
                                         const uint32_t (&b)[2]) {
    asm volatile(
        "mma.sync.aligned.m16n8k8.row.col.f32.tf32.tf32.f32 "
        "{%0,%1,%2,%3}, {%4,%5,%6,%7}, {%8,%9}, {%0,%1,%2,%3};"
        : "+f"(dacc[0]), "+f"(dacc[1]), "+f"(dacc[2]), "+f"(dacc[3])
        : "r"(a[0]), "r"(a[1]), "r"(a[2]), "r"(a[3]), "r"(b[0]), "r"(b[1]));
}

__device__ __forceinline__ float tanh_ap(float x) {
    float y;
    asm("tanh.approx.f32 %0, %1;" : "=f"(y) : "f"(x));
    return y;
}
__device__ __forceinline__ float sig_ap(float x) {
    return fmaf(0.5f, tanh_ap(0.5f * x), 0.5f);
}

__global__ __launch_bounds__(256, 1)
void lstm_mma_kernel(const float* __restrict__ x, float* __restrict__ out) {
    extern __shared__ float sm[];
    float* bias_s = sm + BIAS_OFF;
    float* Bs = sm + B_OFF;
    float* As = sm + A_OFF;

    const int tid = threadIdx.x;
    const int lane = tid & 31;
    const int wid = tid >> 5;
    const int gid = lane >> 2;      // 0..7
    const int tig = lane & 3;       // 0..3
    const int wm = wid & 3;         // 4 m-warps x 32 rows
    const int wj = wid >> 2;        // 2 j-warps x 32 cols
    const int grp = blockIdx.x & 3;
    const int cta_m = blockIdx.x >> 2;   // 0..255

    if (tid < 192) bias_s[tid] = g_bias[grp * 192 + tid];
    {   // copy this group's pre-packed B fragments (96KB, linear)
        const float4* Bg = (const float4*)(g_Wp + (size_t)grp * B_FLOATS);
        float4* Bd = (float4*)Bs;
#pragma unroll
        for (int i = 0; i < 24; ++i) Bd[i * 256 + tid] = Bg[i * 256 + tid];
    }
    {   // first A tile: row-major, padded stride, tf32-rounded
        const float4* src = (const float4*)(x + (size_t)(cta_m * BM) * KDIM);
#pragma unroll
        for (int i = 0; i < 16; ++i) {
            int idx = i * 256 + tid;
            int m = idx >> 5, kq = idx & 31;
            float4 v = src[idx];
            v.x = to_tf32(v.x); v.y = to_tf32(v.y);
            v.z = to_tf32(v.z); v.w = to_tf32(v.w);
            *(float4*)(As + m * A_STRIDE + kq * 4) = v;
        }
    }
    __syncthreads();

    const int rb0 = wm * 32;
    const int jlbase = wj * 32;

    for (int it = 0; it < ITERS; ++it) {
        float acc[2][4][3][4];
#pragma unroll
        for (int mt = 0; mt < 2; ++mt)
#pragma unroll
            for (int jf = 0; jf < 4; ++jf)
#pragma unroll
                for (int g = 0; g < 3; ++g)
#pragma unroll
                    for (int q = 0; q < 4; ++q) acc[mt][jf][g][q] = 0.0f;

#pragma unroll
        for (int ks = 0; ks < 16; ++ks) {
            uint32_t a[2][4];
#pragma unroll
            for (int mt = 0; mt < 2; ++mt) {
                const float* ap = As + (rb0 + mt * 16 + gid) * A_STRIDE + ks * 8 + tig;
                a[mt][0] = __float_as_uint(ap[0]);
                a[mt][1] = __float_as_uint(ap[8 * A_STRIDE]);
                a[mt][2] = __float_as_uint(ap[4]);
                a[mt][3] = __float_as_uint(ap[8 * A_STRIDE + 4]);
            }
#pragma unroll
            for (int jf = 0; jf < 4; ++jf) {
                const int jfg = wj * 4 + jf;
#pragma unroll
                for (int g = 0; g < 3; ++g) {
                    const float* bp = Bs + (((jfg * 3 + g) * 16) + ks) * 64 + lane * 2;
                    uint32_t b[2] = { __float_as_uint(bp[0]), __float_as_uint(bp[1]) };
#pragma unroll
                    for (int mt = 0; mt < 2; ++mt)
                        mma_tf32(acc[mt][jf][g], a[mt], b);
                }
            }
        }
        __syncthreads();   // all warps done reading As

        const bool more = (it + 1 < ITERS);
        float4 pref[16];
        if (more) {   // issue next-tile LDGs; epilogue hides their latency
            const float4* src = (const float4*)
                (x + (size_t)((cta_m + (it + 1) * CTAS_PER_GRP) * BM) * KDIM);
#pragma unroll
            for (int i = 0; i < 16; ++i) pref[i] = src[i * 256 + tid];
        }

        // Epilogue: each thread holds matching i/g/o accs at the same (m,j).
        const int bm = (cta_m + it * CTAS_PER_GRP) * BM;
#pragma unroll
        for (int jf = 0; jf < 4; ++jf) {
            const int jl = jlbase + jf * 8 + 2 * tig;
            const float2 bi = *(const float2*)(bias_s + jl);
            const float2 bg = *(const float2*)(bias_s + 64 + jl);
            const float2 bo = *(const float2*)(bias_s + 128 + jl);
            const int jcol = grp * 64 + jl;
#pragma unroll
            for (int mt = 0; mt < 2; ++mt) {
                const int m0 = bm + rb0 + mt * 16 + gid;
#pragma unroll
                for (int rr = 0; rr < 2; ++rr) {   // row gid / gid+8
                    float i0 = sig_ap(acc[mt][jf][0][rr * 2 + 0] + bi.x);
                    float i1 = sig_ap(acc[mt][jf][0][rr * 2 + 1] + bi.y);
                    float g0 = tanh_ap(acc[mt][jf][1][rr * 2 + 0] + bg.x);
                    float g1 = tanh_ap(acc[mt][jf][1][rr * 2 + 1] + bg.y);
                    float o0 = sig_ap(acc[mt][jf][2][rr * 2 + 0] + bo.x);
                    float o1 = sig_ap(acc[mt][jf][2][rr * 2 + 1] + bo.y);
                    float c0 = i0 * g0, c1 = i1 * g1;
                    float h0 = o0 * tanh_ap(c0), h1 = o1 * tanh_ap(c1);
                    size_t off = (size_t)(m0 + rr * 8) * HID + jcol;
                    *(float2*)(out + off) = make_float2(h0, h1);
                    *(float2*)(out + (size_t)M_TOTAL * HID + off) = make_float2(c0, c1);
                }
            }
        }

        if (more) {   // store prefetched tile (tf32-rounded), then barrier
#pragma unroll
            for (int i = 0; i < 16; ++i) {
                int idx = i * 256 + tid;
                int m = idx >> 5, kq = idx & 31;
                float4 v = pref[i];
                v.x = to_tf32(v.x); v.y = to_tf32(v.y);
                v.z = to_tf32(v.z); v.w = to_tf32(v.w);
                *(float4*)(As + m * A_STRIDE + kq * 4) = v;
            }
            __syncthreads();
        }
    }
}

extern "C" void kernel_launch(void* const* d_in, const int* in_sizes, int n_in,
                              void* d_out, int out_size) {
    const float* x    = (const float*)d_in[0];
    const float* W_ih = (const float*)d_in[1];
    // d_in[2] = W_hh unused (h_prev == 0 in reference)
    const float* b_ih = (const float*)d_in[3];
    const float* b_hh = (const float*)d_in[4];
    float* out = (float*)d_out;

    cudaFuncSetAttribute(lstm_mma_kernel,
                         cudaFuncAttributeMaxDynamicSharedMemorySize, SMEM_BYTES);

    prep_kernel<<<(NPACK * KDIM + 255) / 256, 256>>>(W_ih, b_ih, b_hh);
    lstm_mma_kernel<<<NGRP * CTAS_PER_GRP, 256, SMEM_BYTES>>>(x, out);
}